// round 11
// baseline (speedup 1.0000x reference)
#include <cuda_runtime.h>
#include <cuda_fp16.h>
#include <cstdint>

// Problem shape (fixed by the dataset instance)
#define BB   2
#define HH   32
#define SS   4096
#define DD   128
#define BLK  512
#define NB   (SS / BLK)          // 8
#define NCTA (BB * HH * NB)      // 512
#define NT   512
#define EPS_F 1e-6f

// Smem word strides (4B words; each word = half2 pair along the k dim)
//  W  (phiK pairs)  : [16][KSTR]  bank(4t+g) conflict-free  KSTR%32 == 4
//  WV (V pairs)     : [16][VSTR]  bank(8t+g) conflict-free  VSTR%32 == 8
//  WQ (phiQ words)  : [64][QSTR]  bank(4g+t) conflict-free  QSTR%32 == 4
//  WS (Sdm pairs)   : [64][MSTR]  bank(8t+g) conflict-free  MSTR%32 == 8
#define KSTR 132
#define VSTR 136
#define QSTR 68
#define MSTR 136

#define WS_OFF    0                         // 64 x 136 = 8704 words
#define STAGE_OFF (64 * MSTR)               // 8704
#define BUF_WORDS (16 * KSTR + 16 * VSTR)   // 4288 (x2 buffers = 8576)
#define DEN_OFF   (STAGE_OFF + 2 * BUF_WORDS) // 17280
#define SMEM_WORDS (DEN_OFF + 64)           // 17344
#define SMEM_BYTES (SMEM_WORDS * 4)         // 69376 B -> 2 CTAs/SM

__device__ __forceinline__ float phi_elu1(float y) {
    return y > 0.0f ? y + 1.0f : __expf(y);
}

__device__ __forceinline__ uint32_t pk2(float lo, float hi) {
    __half2 h = __floats2half2_rn(lo, hi);
    return *reinterpret_cast<uint32_t*>(&h);
}

__device__ __forceinline__ void mma_f16(float* c, const uint32_t* a, const uint32_t* b) {
    asm volatile(
        "mma.sync.aligned.m16n8k16.row.col.f32.f16.f16.f32 "
        "{%0,%1,%2,%3}, {%4,%5,%6,%7}, {%8,%9}, {%0,%1,%2,%3};\n"
        : "+f"(c[0]), "+f"(c[1]), "+f"(c[2]), "+f"(c[3])
        : "r"(a[0]), "r"(a[1]), "r"(a[2]), "r"(a[3]), "r"(b[0]), "r"(b[1]));
}

extern "C" __global__ void __launch_bounds__(NT, 2)
lin_attn_w16(const float* __restrict__ q,
             const float* __restrict__ k,
             const float* __restrict__ v,
             const float* __restrict__ sc,
             const float* __restrict__ bi,
             float* __restrict__ out)
{
    extern __shared__ uint32_t sm[];
    uint32_t* WS    = sm + WS_OFF;      // Sdm pairs [64][MSTR]; col 128 = Z, 129..135 = 0
    uint32_t* stage = sm + STAGE_OFF;   // phase1: 2 x (W + WV); phase2: WQ
    float*    den   = (float*)(sm + DEN_OFF);

    const int tid  = threadIdx.x;
    const int lane = tid & 31;
    const int w    = tid >> 5;          // warp 0..15
    const int g    = lane >> 2;         // 0..7
    const int t    = lane & 3;          // 0..3

    const int c  = blockIdx.x;
    const int n  = c % NB;
    const int bh = c / NB;
    const int h  = bh % HH;
    const long gbase = ((long)bh * SS + (long)n * BLK) * DD;

    const float* qb = q + gbase;
    const float* kb = k + gbase;
    const float* vb = v + gbase;
    float*       ob = out + gbase;

    const int c4 = lane * 4;            // producer d-columns c4..c4+3
    const float4 sc4 = *(const float4*)(sc + h * DD + c4);
    const float4 bi4 = *(const float4*)(bi + h * DD + c4);

    // ====== Phase 1: S^T[m][d] = V^T x phiK  (A = V^T, B = phiK, k = s) ====
    // chunk = 32 s-rows (16 pairs); warp w packs pair (2w, 2w+1)
    // warp tiling: wa = w&3 -> 32 m-rows; wb = w>>2 -> 32 d-cols
    const int wa = w & 3;
    const int wb = w >> 2;
    const int m0 = wa * 32;
    const int d0 = wb * 32;

    float acc[2][4][4];                 // [mt][dt][c]
    #pragma unroll
    for (int a = 0; a < 2; ++a)
        #pragma unroll
        for (int b = 0; b < 4; ++b)
            #pragma unroll
            for (int r = 0; r < 4; ++r) acc[a][b][r] = 0.0f;

    float4 zacc = make_float4(0.f, 0.f, 0.f, 0.f);
    float4 kv0, kv1, vv0, vv1;

#define LOADCH(ch) do {                                                     \
        const float* kc_ = kb + (long)((ch) * 32 + 2 * w) * DD;             \
        const float* vc_ = vb + (long)((ch) * 32 + 2 * w) * DD;             \
        kv0 = *(const float4*)(kc_ + c4);                                   \
        kv1 = *(const float4*)(kc_ + DD + c4);                              \
        vv0 = *(const float4*)(vc_ + c4);                                   \
        vv1 = *(const float4*)(vc_ + DD + c4);                              \
    } while (0)

    // pack half2(s-row 2w, 2w+1) per d column; one uint4 store each
#define STORECH(pk_, pv_) do {                                              \
        float a0 = phi_elu1(fmaf(kv0.x, sc4.x, bi4.x));                     \
        float a1 = phi_elu1(fmaf(kv0.y, sc4.y, bi4.y));                     \
        float a2 = phi_elu1(fmaf(kv0.z, sc4.z, bi4.z));                     \
        float a3 = phi_elu1(fmaf(kv0.w, sc4.w, bi4.w));                     \
        float b0 = phi_elu1(fmaf(kv1.x, sc4.x, bi4.x));                     \
        float b1 = phi_elu1(fmaf(kv1.y, sc4.y, bi4.y));                     \
        float b2 = phi_elu1(fmaf(kv1.z, sc4.z, bi4.z));                     \
        float b3 = phi_elu1(fmaf(kv1.w, sc4.w, bi4.w));                     \
        zacc.x += a0 + b0; zacc.y += a1 + b1;                               \
        zacc.z += a2 + b2; zacc.w += a3 + b3;                               \
        uint4 ku_ = make_uint4(pk2(a0, b0), pk2(a1, b1),                    \
                               pk2(a2, b2), pk2(a3, b3));                   \
        *(uint4*)((pk_) + w * KSTR + c4) = ku_;                             \
        uint4 vu_ = make_uint4(pk2(vv0.x, vv1.x), pk2(vv0.y, vv1.y),        \
                               pk2(vv0.z, vv1.z), pk2(vv0.w, vv1.w));       \
        *(uint4*)((pv_) + w * VSTR + c4) = vu_;                             \
    } while (0)

    LOADCH(0);
    STORECH(stage, stage + 16 * KSTR);
    LOADCH(1);
    __syncthreads();

    for (int ch = 0; ch < BLK / 32; ++ch) {      // 16 chunks of 32 rows
        const int p = ch & 1;
        uint32_t* pk = stage + p * BUF_WORDS;
        uint32_t* pv = pk + 16 * KSTR;

        if (ch < BLK / 32 - 1) {
            uint32_t* npk = stage + (p ^ 1) * BUF_WORDS;
            STORECH(npk, npk + 16 * KSTR);
        }
        if (ch < BLK / 32 - 2) LOADCH(ch + 2);

        // two k=16 steps over the 32 staged s-rows (pairs 0..7, 8..15)
        #pragma unroll
        for (int ks = 0; ks < 2; ++ks) {
            const int sb = ks * 8;
            uint32_t B[4][2];
            #pragma unroll
            for (int dt = 0; dt < 4; ++dt) {
                const int d = d0 + dt * 8 + g;
                B[dt][0] = pk[(sb + t)     * KSTR + d];
                B[dt][1] = pk[(sb + t + 4) * KSTR + d];
            }
            #pragma unroll
            for (int mt = 0; mt < 2; ++mt) {
                const int m = m0 + mt * 16 + g;
                uint32_t A[4];
                A[0] = pv[(sb + t)     * VSTR + m];
                A[1] = pv[(sb + t)     * VSTR + m + 8];
                A[2] = pv[(sb + t + 4) * VSTR + m];
                A[3] = pv[(sb + t + 4) * VSTR + m + 8];
                #pragma unroll
                for (int dt = 0; dt < 4; ++dt)
                    mma_f16(acc[mt][dt], A, B[dt]);
            }
        }
        __syncthreads();
    }

    // ===== epilogue: S^T tiles -> WS[d/2][m] as half2 pairs along d =====
    #pragma unroll
    for (int mt = 0; mt < 2; ++mt) {
        const int m = m0 + mt * 16 + g;
        #pragma unroll
        for (int dt = 0; dt < 4; ++dt) {
            const int dp = wb * 16 + dt * 4 + t;
            WS[dp * MSTR + m]     = pk2(acc[mt][dt][0], acc[mt][dt][1]);
            WS[dp * MSTR + m + 8] = pk2(acc[mt][dt][2], acc[mt][dt][3]);
        }
    }

    // prefetch Q chunk 0 (rows w + 16j, j<4) -- overlaps Z reduction
    float4 qreg[4];
    #pragma unroll
    for (int j = 0; j < 4; ++j)
        qreg[j] = *(const float4*)(qb + (long)(w + 16 * j) * DD + c4);

    // reduce Z -> WS column 128 ; zero columns 129..135
    float* zred = (float*)stage;        // 16 x 128 floats (phase-1 bufs dead)
    *(float4*)(zred + w * DD + c4) = zacc;
    __syncthreads();
    if (tid < 64) {
        float s0 = 0.0f, s1 = 0.0f;
        #pragma unroll
        for (int r = 0; r < 16; ++r) {
            s0 += zred[r * DD + 2 * tid];
            s1 += zred[r * DD + 2 * tid + 1];
        }
        WS[tid * MSTR + 128] = pk2(s0, s1);
    }
    for (int idx = tid; idx < 64 * 7; idx += NT) {
        const int dp = idx / 7;
        const int cc = 129 + idx % 7;
        WS[dp * MSTR + cc] = 0u;
    }
    __syncthreads();

    // ====== Phase 2: out = phiQ x [Sdm | Z] ; den fused as column 128 ======
    // chunk = 64 s-rows; warp grid 2s x 8m: tile 32s x 16m (+ Z for wm==0)
    uint32_t* WQ = stage;               // [64][QSTR] half2 words along d
    const int ws  = w & 1;
    const int wm  = w >> 1;
    const int s0q = ws * 32;
    const int m0q = wm * 16;

    for (int chq = 0; chq < BLK / 64; ++chq) {   // 8 chunks
        // stage phiQ: rows w + 16j (j<4), words 2*lane, 2*lane+1
        #pragma unroll
        for (int j = 0; j < 4; ++j) {
            const int r = w + 16 * j;
            float p0 = phi_elu1(fmaf(qreg[j].x, sc4.x, bi4.x));
            float p1 = phi_elu1(fmaf(qreg[j].y, sc4.y, bi4.y));
            float p2 = phi_elu1(fmaf(qreg[j].z, sc4.z, bi4.z));
            float p3 = phi_elu1(fmaf(qreg[j].w, sc4.w, bi4.w));
            uint2 qu = make_uint2(pk2(p0, p1), pk2(p2, p3));
            *(uint2*)(WQ + r * QSTR + 2 * lane) = qu;
        }
        __syncthreads();

        // prefetch next Q chunk (overlaps mma)
        if (chq < BLK / 64 - 1) {
            const float* qc = qb + (long)(chq + 1) * 64 * DD;
            #pragma unroll
            for (int j = 0; j < 4; ++j)
                qreg[j] = *(const float4*)(qc + (long)(w + 16 * j) * DD + c4);
        }

        float accq[2][2][4];
        float az[2][4];
        #pragma unroll
        for (int st = 0; st < 2; ++st) {
            #pragma unroll
            for (int mt = 0; mt < 2; ++mt)
                #pragma unroll
                for (int r = 0; r < 4; ++r) accq[st][mt][r] = 0.0f;
            #pragma unroll
            for (int r = 0; r < 4; ++r) az[st][r] = 0.0f;
        }

        #pragma unroll
        for (int kk = 0; kk < DD / 16; ++kk) {   // 8 k-steps of 16
            uint32_t A[2][4];
            #pragma unroll
            for (int st = 0; st < 2; ++st) {
                const int row = s0q + st * 16;
                A[st][0] = WQ[(row + g)     * QSTR + 8 * kk + t];
                A[st][1] = WQ[(row + g + 8) * QSTR + 8 * kk + t];
                A[st][2] = WQ[(row + g)     * QSTR + 8 * kk + t + 4];
                A[st][3] = WQ[(row + g + 8) * QSTR + 8 * kk + t + 4];
            }
            #pragma unroll
            for (int mt = 0; mt < 2; ++mt) {
                const int m = m0q + mt * 8 + g;
                uint32_t B[2];
                B[0] = WS[(8 * kk + t)     * MSTR + m];
                B[1] = WS[(8 * kk + t + 4) * MSTR + m];
                mma_f16(accq[0][mt], A[0], B);
                mma_f16(accq[1][mt], A[1], B);
            }
            if (wm == 0) {
                uint32_t B[2];
                B[0] = WS[(8 * kk + t)     * MSTR + 128 + g];
                B[1] = WS[(8 * kk + t + 4) * MSTR + 128 + g];
                mma_f16(az[0], A[0], B);
                mma_f16(az[1], A[1], B);
            }
        }

        // den = Z-tile col 128 (t==0: c0 row g, c2 row g+8); warps w=0,1
        if (wm == 0 && t == 0) {
            #pragma unroll
            for (int st = 0; st < 2; ++st) {
                den[s0q + st * 16 + g]     = az[st][0] + EPS_F;
                den[s0q + st * 16 + g + 8] = az[st][2] + EPS_F;
            }
        }
        __syncthreads();   // den visible; WQ reads complete before restage

        // epilogue: scale by 1/den, store
        #pragma unroll
        for (int st = 0; st < 2; ++st) {
            const int rr   = s0q + st * 16 + g;
            const int r0   = chq * 64 + rr;
            const float i0 = 1.0f / den[rr];
            const float i1 = 1.0f / den[rr + 8];
            #pragma unroll
            for (int mt = 0; mt < 2; ++mt) {
                const int m = m0q + mt * 8 + 2 * t;
                *(float2*)(ob + (long)r0 * DD + m) =
                    make_float2(accq[st][mt][0] * i0, accq[st][mt][1] * i0);
                *(float2*)(ob + (long)(r0 + 8) * DD + m) =
                    make_float2(accq[st][mt][2] * i1, accq[st][mt][3] * i1);
            }
        }
    }
}

extern "C" void kernel_launch(void* const* d_in, const int* in_sizes, int n_in,
                              void* d_out, int out_size) {
    const float* q  = (const float*)d_in[0];
    const float* k  = (const float*)d_in[1];
    const float* v  = (const float*)d_in[2];
    const float* sc = (const float*)d_in[3];
    const float* bi = (const float*)d_in[4];
    float* out = (float*)d_out;

    cudaFuncSetAttribute(lin_attn_w16,
                         cudaFuncAttributeMaxDynamicSharedMemorySize, SMEM_BYTES);
    lin_attn_w16<<<NCTA, NT, SMEM_BYTES>>>(q, k, v, sc, bi, out);
}

// round 12
// speedup vs baseline: 1.6276x; 1.6276x over previous
#include <cuda_runtime.h>
#include <cuda_fp16.h>
#include <cstdint>

// Problem shape (fixed by the dataset instance)
#define BB   2
#define HH   32
#define SS   4096
#define DD   128
#define BLK  512
#define NB   (SS / BLK)          // 8
#define NBLKS (BB * HH * NB)     // 512 logical blocks
#define NCTA  256                // persistent: each CTA does 2 blocks
#define NT   256
#define EPS_F 1e-6f

// Smem word strides (4B words, each word = half2 pair along the k dim)
//  W  (phiK pairs)  : [8][KSTR]  bank(4t+g) conflict-free   KSTR%32 == 4
//  WV (V pairs)     : [8][VSTR]  bank(8t+g) conflict-free   VSTR%32 == 8
//  WQ (phiQ words)  : [64][QSTR] bank(4g+t) conflict-free   QSTR%32 == 4
//  WS (Sdm pairs)   : [64][MSTR] bank(8t+g) conflict-free   MSTR%32 == 8
#define KSTR 132
#define VSTR 136
#define QSTR 68
#define MSTR 136

#define WS_OFF    0                        // 64 x 136 = 8704 words
#define STAGE_OFF (64 * MSTR)              // 8704
#define BUF_WORDS (8 * KSTR + 8 * VSTR)    // 2144 (phase-1, x2 buffers = 4288)
#define DEN_OFF   (STAGE_OFF + 64 * QSTR)  // 8704 + 4352 = 13056 (WQ >= 2 bufs)
#define SMEM_WORDS (DEN_OFF + 64)          // 13120
#define SMEM_BYTES (SMEM_WORDS * 4)        // 52480 B -> 2 CTAs/SM

__device__ __forceinline__ float phi_elu1(float y) {
    return y > 0.0f ? y + 1.0f : __expf(y);
}

__device__ __forceinline__ uint32_t pk2(float lo, float hi) {
    __half2 h = __floats2half2_rn(lo, hi);
    return *reinterpret_cast<uint32_t*>(&h);
}

__device__ __forceinline__ void mma_f16(float* c, const uint32_t* a, const uint32_t* b) {
    asm volatile(
        "mma.sync.aligned.m16n8k16.row.col.f32.f16.f16.f32 "
        "{%0,%1,%2,%3}, {%4,%5,%6,%7}, {%8,%9}, {%0,%1,%2,%3};\n"
        : "+f"(c[0]), "+f"(c[1]), "+f"(c[2]), "+f"(c[3])
        : "r"(a[0]), "r"(a[1]), "r"(a[2]), "r"(a[3]), "r"(b[0]), "r"(b[1]));
}

extern "C" __global__ void __launch_bounds__(NT, 2)
lin_attn_pers(const float* __restrict__ q,
              const float* __restrict__ k,
              const float* __restrict__ v,
              const float* __restrict__ sc,
              const float* __restrict__ bi,
              float* __restrict__ out)
{
    extern __shared__ uint32_t sm[];
    uint32_t* WS    = sm + WS_OFF;      // Sdm pairs [64][MSTR]; col 128 = Z, 129..135 = 0
    uint32_t* stage = sm + STAGE_OFF;   // phase1: 2 x (W + WV); phase2: WQ
    float*    den   = (float*)(sm + DEN_OFF);

    const int tid  = threadIdx.x;
    const int lane = tid & 31;
    const int w    = tid >> 5;          // warp 0..7
    const int g    = lane >> 2;         // 0..7
    const int t    = lane & 3;          // 0..3

    const int lrow = w;                 // producer handles s-row pair (2w, 2w+1)
    const int c4   = lane * 4;          // producer d-columns c4..c4+3

    // phase-1 warp tiling: wa = m half (64), wb = d quarter (32)
    const int wa = w & 1;
    const int wb = w >> 1;
    // phase-2 warp tiling: 2s x 4m
    const int wsq = w & 1;
    const int wm  = w >> 1;
    const int s0  = wsq * 32;
    const int m0  = wm * 32;

    for (int blk_it = 0; blk_it < NBLKS / NCTA; ++blk_it) {
        const int c  = blockIdx.x + blk_it * NCTA;
        const int n  = c % NB;
        const int bh = c / NB;
        const int h  = bh % HH;
        const long gbase = ((long)bh * SS + (long)n * BLK) * DD;

        const float* qb = q + gbase;
        const float* kb = k + gbase;
        const float* vb = v + gbase;
        float*       ob = out + gbase;

        const float4 sc4 = *(const float4*)(sc + h * DD + c4);
        const float4 bi4 = *(const float4*)(bi + h * DD + c4);

        // ====== Phase 1: S^T[m][d] = V^T x phiK  (A = V^T, B = phiK, k = s) ====
        float acc[4][4][4];                 // [mt][dt][c]
        #pragma unroll
        for (int a = 0; a < 4; ++a)
            #pragma unroll
            for (int b = 0; b < 4; ++b)
                #pragma unroll
                for (int r = 0; r < 4; ++r) acc[a][b][r] = 0.0f;

        float4 zacc = make_float4(0.f, 0.f, 0.f, 0.f);
        float4 kv0, kv1, vv0, vv1;

#define LOADCH(ch) do {                                                     \
        const float* kc_ = kb + (long)((ch) * 16 + 2 * lrow) * DD;          \
        const float* vc_ = vb + (long)((ch) * 16 + 2 * lrow) * DD;          \
        kv0 = *(const float4*)(kc_ + c4);                                   \
        kv1 = *(const float4*)(kc_ + DD + c4);                              \
        vv0 = *(const float4*)(vc_ + c4);                                   \
        vv1 = *(const float4*)(vc_ + DD + c4);                              \
    } while (0)

#define STORECH(pk_, pv_) do {                                              \
        float a0 = phi_elu1(fmaf(kv0.x, sc4.x, bi4.x));                     \
        float a1 = phi_elu1(fmaf(kv0.y, sc4.y, bi4.y));                     \
        float a2 = phi_elu1(fmaf(kv0.z, sc4.z, bi4.z));                     \
        float a3 = phi_elu1(fmaf(kv0.w, sc4.w, bi4.w));                     \
        float b0 = phi_elu1(fmaf(kv1.x, sc4.x, bi4.x));                     \
        float b1 = phi_elu1(fmaf(kv1.y, sc4.y, bi4.y));                     \
        float b2 = phi_elu1(fmaf(kv1.z, sc4.z, bi4.z));                     \
        float b3 = phi_elu1(fmaf(kv1.w, sc4.w, bi4.w));                     \
        zacc.x += a0 + b0; zacc.y += a1 + b1;                               \
        zacc.z += a2 + b2; zacc.w += a3 + b3;                               \
        uint4 ku_ = make_uint4(pk2(a0, b0), pk2(a1, b1),                    \
                               pk2(a2, b2), pk2(a3, b3));                   \
        *(uint4*)((pk_) + lrow * KSTR + c4) = ku_;                          \
        uint4 vu_ = make_uint4(pk2(vv0.x, vv1.x), pk2(vv0.y, vv1.y),        \
                               pk2(vv0.z, vv1.z), pk2(vv0.w, vv1.w));       \
        *(uint4*)((pv_) + lrow * VSTR + c4) = vu_;                          \
    } while (0)

        LOADCH(0);
        STORECH(stage, stage + 8 * KSTR);
        LOADCH(1);
        __syncthreads();

        for (int ch = 0; ch < BLK / 16; ++ch) {
            const int p = ch & 1;
            uint32_t* pk = stage + p * BUF_WORDS;
            uint32_t* pv = pk + 8 * KSTR;

            if (ch < BLK / 16 - 1) {
                uint32_t* npk = stage + (p ^ 1) * BUF_WORDS;
                STORECH(npk, npk + 8 * KSTR);
            }
            if (ch < BLK / 16 - 2) LOADCH(ch + 2);

            // one k=16 step over the 16 staged s-rows
            uint32_t B[4][2];
            #pragma unroll
            for (int dt = 0; dt < 4; ++dt) {
                const int d = wb * 32 + dt * 8 + g;
                B[dt][0] = pk[t * KSTR + d];
                B[dt][1] = pk[(t + 4) * KSTR + d];
            }
            #pragma unroll
            for (int mt = 0; mt < 4; ++mt) {
                const int m = wa * 64 + mt * 16 + g;
                uint32_t A[4];
                A[0] = pv[t * VSTR + m];
                A[1] = pv[t * VSTR + m + 8];
                A[2] = pv[(t + 4) * VSTR + m];
                A[3] = pv[(t + 4) * VSTR + m + 8];
                #pragma unroll
                for (int dt = 0; dt < 4; ++dt)
                    mma_f16(acc[mt][dt], A, B[dt]);
            }
            __syncthreads();
        }

        // ===== epilogue: S^T tiles -> WS[d/2][m] as half2 pairs along d =====
        #pragma unroll
        for (int mt = 0; mt < 4; ++mt) {
            const int m = wa * 64 + mt * 16 + g;
            #pragma unroll
            for (int dt = 0; dt < 4; ++dt) {
                const int dp = wb * 16 + dt * 4 + t;
                WS[dp * MSTR + m]     = pk2(acc[mt][dt][0], acc[mt][dt][1]);
                WS[dp * MSTR + m + 8] = pk2(acc[mt][dt][2], acc[mt][dt][3]);
            }
        }

        // prefetch Q chunk 0 (overlaps Z reduction)
        float4 qreg[8];
        #pragma unroll
        for (int j = 0; j < 8; ++j)
            qreg[j] = *(const float4*)(qb + (long)(lrow + 8 * j) * DD + c4);

        // reduce Z -> WS column 128 ; zero columns 129..135
        float* zred = (float*)stage;        // 8 x 128 floats (phase-1 bufs dead)
        *(float4*)(zred + lrow * DD + c4) = zacc;
        __syncthreads();
        if (tid < 64) {
            float z0 = 0.0f, z1 = 0.0f;
            #pragma unroll
            for (int r = 0; r < 8; ++r) {
                z0 += zred[r * DD + 2 * tid];
                z1 += zred[r * DD + 2 * tid + 1];
            }
            WS[tid * MSTR + 128] = pk2(z0, z1);
        }
        for (int idx = tid; idx < 64 * 7; idx += NT) {
            const int dp = idx / 7;
            const int cc = 129 + idx % 7;
            WS[dp * MSTR + cc] = 0u;
        }
        __syncthreads();

        // ====== Phase 2: out = phiQ x [Sdm | Z] ; den fused as column 128 ======
        uint32_t* WQ = stage;               // [64][QSTR] half2 words along d

        for (int chq = 0; chq < BLK / 64; ++chq) {
            // stage phiQ: row r, d c4..c4+3 -> words 2*lane, 2*lane+1 (uint2)
            #pragma unroll
            for (int j = 0; j < 8; ++j) {
                const int r = lrow + 8 * j;
                float p0 = phi_elu1(fmaf(qreg[j].x, sc4.x, bi4.x));
                float p1 = phi_elu1(fmaf(qreg[j].y, sc4.y, bi4.y));
                float p2 = phi_elu1(fmaf(qreg[j].z, sc4.z, bi4.z));
                float p3 = phi_elu1(fmaf(qreg[j].w, sc4.w, bi4.w));
                uint2 qu = make_uint2(pk2(p0, p1), pk2(p2, p3));
                *(uint2*)(WQ + r * QSTR + 2 * lane) = qu;
            }
            __syncthreads();

            // prefetch next Q chunk (overlaps mma)
            if (chq < BLK / 64 - 1) {
                const float* qc = qb + (long)(chq + 1) * 64 * DD;
                #pragma unroll
                for (int j = 0; j < 8; ++j)
                    qreg[j] = *(const float4*)(qc + (long)(lrow + 8 * j) * DD + c4);
            }

            float accq[2][5][4];
            #pragma unroll
            for (int st = 0; st < 2; ++st)
                #pragma unroll
                for (int mt = 0; mt < 5; ++mt)
                    #pragma unroll
                    for (int r = 0; r < 4; ++r) accq[st][mt][r] = 0.0f;

            #pragma unroll
            for (int kk = 0; kk < DD / 16; ++kk) {       // 8 k-steps of 16
                uint32_t A[2][4];
                #pragma unroll
                for (int st = 0; st < 2; ++st) {
                    const int row = s0 + st * 16;
                    A[st][0] = WQ[(row + g)     * QSTR + 8 * kk + t];
                    A[st][1] = WQ[(row + g + 8) * QSTR + 8 * kk + t];
                    A[st][2] = WQ[(row + g)     * QSTR + 8 * kk + t + 4];
                    A[st][3] = WQ[(row + g + 8) * QSTR + 8 * kk + t + 4];
                }
                #pragma unroll
                for (int mt = 0; mt < 4; ++mt) {
                    const int m = m0 + mt * 8 + g;
                    uint32_t B[2];
                    B[0] = WS[(8 * kk + t)     * MSTR + m];
                    B[1] = WS[(8 * kk + t + 4) * MSTR + m];
                    mma_f16(accq[0][mt], A[0], B);
                    mma_f16(accq[1][mt], A[1], B);
                }
                if (wm == 0) {
                    uint32_t B[2];
                    B[0] = WS[(8 * kk + t)     * MSTR + 128 + g];
                    B[1] = WS[(8 * kk + t + 4) * MSTR + 128 + g];
                    mma_f16(accq[0][4], A[0], B);
                    mma_f16(accq[1][4], A[1], B);
                }
            }

            // den = Z-tile col 128 (t==0: c0 row g, c2 row g+8)
            if (wm == 0 && t == 0) {
                #pragma unroll
                for (int st = 0; st < 2; ++st) {
                    den[s0 + st * 16 + g]     = accq[st][4][0] + EPS_F;
                    den[s0 + st * 16 + g + 8] = accq[st][4][2] + EPS_F;
                }
            }
            __syncthreads();   // den visible; WQ reads complete before restage

            // epilogue: scale by 1/den, store
            #pragma unroll
            for (int st = 0; st < 2; ++st) {
                const int rr   = s0 + st * 16 + g;
                const int r0   = chq * 64 + rr;
                const float i0 = 1.0f / den[rr];
                const float i1 = 1.0f / den[rr + 8];
                #pragma unroll
                for (int mt = 0; mt < 4; ++mt) {
                    const int m = m0 + mt * 8 + 2 * t;
                    *(float2*)(ob + (long)r0 * DD + m) =
                        make_float2(accq[st][mt][0] * i0, accq[st][mt][1] * i0);
                    *(float2*)(ob + (long)(r0 + 8) * DD + m) =
                        make_float2(accq[st][mt][2] * i1, accq[st][mt][3] * i1);
                }
            }
        }
#undef LOADCH
#undef STORECH
    }
}

extern "C" void kernel_launch(void* const* d_in, const int* in_sizes, int n_in,
                              void* d_out, int out_size) {
    const float* q  = (const float*)d_in[0];
    const float* k  = (const float*)d_in[1];
    const float* v  = (const float*)d_in[2];
    const float* sc = (const float*)d_in[3];
    const float* bi = (const float*)d_in[4];
    float* out = (float*)d_out;

    cudaFuncSetAttribute(lin_attn_pers,
                         cudaFuncAttributeMaxDynamicSharedMemorySize, SMEM_BYTES);
    lin_attn_pers<<<NCTA, NT, SMEM_BYTES>>>(q, k, v, sc, bi, out);
}

// round 13
// speedup vs baseline: 1.7098x; 1.0505x over previous
#include <cuda_runtime.h>
#include <cuda_fp16.h>
#include <cstdint>

// Problem shape (fixed by the dataset instance)
#define BB   2
#define HH   32
#define SS   4096
#define DD   128
#define BLK  512
#define NB   (SS / BLK)          // 8
#define NCTA (BB * HH * NB)      // 512
#define NT   256
#define EPS_F 1e-6f

// Phase-1 staging strides (4B words; word = half2 pair along k=s) — proven
#define KSTR 132   // phiK [8][KSTR]  bank(4t+g) conflict-free
#define VSTR 136   // V    [8][VSTR]  bank(8t+g) conflict-free
// Phase-2 ldmatrix tiles (word = half2 pair along d, d contiguous)
#define WSTR 68    // WS2 [136][WSTR]: rows m (128=Z, 129..135=0)
#define QSTR 68    // WQ  [64][QSTR] x2 buffers

#define WS2_OFF 0
#define WQ_OFF  (136 * WSTR)                // 9248
#define WQ_BUF  (64 * QSTR)                 // 4352 words per buffer
#define BUF_WORDS (8 * KSTR + 8 * VSTR)     // 2144 (phase-1, union with WQ)
#define SMEM_WORDS (WQ_OFF + 2 * WQ_BUF)    // 17952
#define SMEM_BYTES (SMEM_WORDS * 4)         // 71808 B -> 2 CTAs/SM

__device__ __forceinline__ float phi_elu1(float y) {
    return y > 0.0f ? y + 1.0f : __expf(y);
}

__device__ __forceinline__ uint32_t pk2(float lo, float hi) {
    __half2 h = __floats2half2_rn(lo, hi);
    return *reinterpret_cast<uint32_t*>(&h);
}

__device__ __forceinline__ uint32_t smem_u32(const void* p) {
    uint32_t a;
    asm("{ .reg .u64 t; cvta.to.shared.u64 t, %1; cvt.u32.u64 %0, t; }"
        : "=r"(a) : "l"(p));
    return a;
}

__device__ __forceinline__ void mma_f16(float* c, const uint32_t* a, const uint32_t* b) {
    asm volatile(
        "mma.sync.aligned.m16n8k16.row.col.f32.f16.f16.f32 "
        "{%0,%1,%2,%3}, {%4,%5,%6,%7}, {%8,%9}, {%0,%1,%2,%3};\n"
        : "+f"(c[0]), "+f"(c[1]), "+f"(c[2]), "+f"(c[3])
        : "r"(a[0]), "r"(a[1]), "r"(a[2]), "r"(a[3]), "r"(b[0]), "r"(b[1]));
}

#define LDSM4(r, addr)                                                      \
    asm volatile("ldmatrix.sync.aligned.m8n8.x4.shared.b16 "                \
                 "{%0,%1,%2,%3}, [%4];"                                     \
                 : "=r"((r)[0]), "=r"((r)[1]), "=r"((r)[2]), "=r"((r)[3])   \
                 : "r"(addr))
#define LDSM2(r, addr)                                                      \
    asm volatile("ldmatrix.sync.aligned.m8n8.x2.shared.b16 "                \
                 "{%0,%1}, [%2];"                                           \
                 : "=r"((r)[0]), "=r"((r)[1])                               \
                 : "r"(addr))

extern "C" __global__ void __launch_bounds__(NT, 2)
lin_attn_ldsm(const float* __restrict__ q,
              const float* __restrict__ k,
              const float* __restrict__ v,
              const float* __restrict__ sc,
              const float* __restrict__ bi,
              float* __restrict__ out)
{
    extern __shared__ uint32_t sm[];
    uint32_t* WS2   = sm + WS2_OFF;     // [136][WSTR] half2 along d; row 128 = Z
    uint32_t* stage = sm + WQ_OFF;      // phase1: 2x(W+WV); phase2: WQ x2

    const int tid  = threadIdx.x;
    const int lane = tid & 31;
    const int w    = tid >> 5;          // warp 0..7
    const int g    = lane >> 2;         // 0..7
    const int t    = lane & 3;          // 0..3

    const int c  = blockIdx.x;
    const int n  = c % NB;
    const int bh = c / NB;
    const int h  = bh % HH;
    const long gbase = ((long)bh * SS + (long)n * BLK) * DD;

    const float* qb = q + gbase;
    const float* kb = k + gbase;
    const float* vb = v + gbase;
    float*       ob = out + gbase;

    const int lrow = w;                 // producer handles s-row pair (2w, 2w+1)
    const int c4   = lane * 4;          // producer d-columns c4..c4+3
    const float4 sc4 = *(const float4*)(sc + h * DD + c4);
    const float4 bi4 = *(const float4*)(bi + h * DD + c4);

    // ====== Phase 1: S^T[m][d] = V^T x phiK  (A = V^T, B = phiK, k = s) ====
    const int wa = w & 1;               // m half (64)
    const int wb = w >> 1;              // d quarter (32)

    float acc[4][4][4];                 // [mt][dt][c]
    #pragma unroll
    for (int a = 0; a < 4; ++a)
        #pragma unroll
        for (int b = 0; b < 4; ++b)
            #pragma unroll
            for (int r = 0; r < 4; ++r) acc[a][b][r] = 0.0f;

    float4 zacc = make_float4(0.f, 0.f, 0.f, 0.f);
    float4 kv0, kv1, vv0, vv1;

#define LOADCH(ch) do {                                                     \
        const float* kc_ = kb + (long)((ch) * 16 + 2 * lrow) * DD;          \
        const float* vc_ = vb + (long)((ch) * 16 + 2 * lrow) * DD;          \
        kv0 = *(const float4*)(kc_ + c4);                                   \
        kv1 = *(const float4*)(kc_ + DD + c4);                              \
        vv0 = *(const float4*)(vc_ + c4);                                   \
        vv1 = *(const float4*)(vc_ + DD + c4);                              \
    } while (0)

#define STORECH(pk_, pv_) do {                                              \
        float a0 = phi_elu1(fmaf(kv0.x, sc4.x, bi4.x));                     \
        float a1 = phi_elu1(fmaf(kv0.y, sc4.y, bi4.y));                     \
        float a2 = phi_elu1(fmaf(kv0.z, sc4.z, bi4.z));                     \
        float a3 = phi_elu1(fmaf(kv0.w, sc4.w, bi4.w));                     \
        float b0 = phi_elu1(fmaf(kv1.x, sc4.x, bi4.x));                     \
        float b1 = phi_elu1(fmaf(kv1.y, sc4.y, bi4.y));                     \
        float b2 = phi_elu1(fmaf(kv1.z, sc4.z, bi4.z));                     \
        float b3 = phi_elu1(fmaf(kv1.w, sc4.w, bi4.w));                     \
        zacc.x += a0 + b0; zacc.y += a1 + b1;                               \
        zacc.z += a2 + b2; zacc.w += a3 + b3;                               \
        uint4 ku_ = make_uint4(pk2(a0, b0), pk2(a1, b1),                    \
                               pk2(a2, b2), pk2(a3, b3));                   \
        *(uint4*)((pk_) + lrow * KSTR + c4) = ku_;                          \
        uint4 vu_ = make_uint4(pk2(vv0.x, vv1.x), pk2(vv0.y, vv1.y),        \
                               pk2(vv0.z, vv1.z), pk2(vv0.w, vv1.w));       \
        *(uint4*)((pv_) + lrow * VSTR + c4) = vu_;                          \
    } while (0)

    LOADCH(0);
    STORECH(stage, stage + 8 * KSTR);
    LOADCH(1);
    __syncthreads();

    for (int ch = 0; ch < BLK / 16; ++ch) {
        const int p = ch & 1;
        uint32_t* pk = stage + p * BUF_WORDS;
        uint32_t* pv = pk + 8 * KSTR;

        if (ch < BLK / 16 - 1) {
            uint32_t* npk = stage + (p ^ 1) * BUF_WORDS;
            STORECH(npk, npk + 8 * KSTR);
        }
        if (ch < BLK / 16 - 2) LOADCH(ch + 2);

        uint32_t B[4][2];
        #pragma unroll
        for (int dt = 0; dt < 4; ++dt) {
            const int d = wb * 32 + dt * 8 + g;
            B[dt][0] = pk[t * KSTR + d];
            B[dt][1] = pk[(t + 4) * KSTR + d];
        }
        #pragma unroll
        for (int mt = 0; mt < 4; ++mt) {
            const int m = wa * 64 + mt * 16 + g;
            uint32_t A[4];
            A[0] = pv[t * VSTR + m];
            A[1] = pv[t * VSTR + m + 8];
            A[2] = pv[(t + 4) * VSTR + m];
            A[3] = pv[(t + 4) * VSTR + m + 8];
            #pragma unroll
            for (int dt = 0; dt < 4; ++dt)
                mma_f16(acc[mt][dt], A, B[dt]);
        }
        __syncthreads();
    }

    // ===== epilogue: S^T -> WS2[m][d-halves] (c0,c1 are d-adjacent) =====
    #pragma unroll
    for (int mt = 0; mt < 4; ++mt) {
        const int m = wa * 64 + mt * 16 + g;
        #pragma unroll
        for (int dt = 0; dt < 4; ++dt) {
            const int dw = wb * 16 + dt * 4 + t;       // d word index
            WS2[m       * WSTR + dw] = pk2(acc[mt][dt][0], acc[mt][dt][1]);
            WS2[(m + 8) * WSTR + dw] = pk2(acc[mt][dt][2], acc[mt][dt][3]);
        }
    }

    // prefetch Q chunk 0 (overlaps Z reduction)
    float4 qreg[8];
    #pragma unroll
    for (int j = 0; j < 8; ++j)
        qreg[j] = *(const float4*)(qb + (long)(lrow + 8 * j) * DD + c4);

    // reduce Z -> WS2 row 128 ; zero rows 129..135
    float* zred = (float*)stage;
    *(float4*)(zred + lrow * DD + c4) = zacc;
    __syncthreads();
    if (tid < 64) {
        float z0 = 0.0f, z1 = 0.0f;
        #pragma unroll
        for (int r = 0; r < 8; ++r) {
            z0 += zred[r * DD + 2 * tid];
            z1 += zred[r * DD + 2 * tid + 1];
        }
        WS2[128 * WSTR + tid] = pk2(z0, z1);
    }
    for (int idx = tid; idx < 7 * WSTR; idx += NT)
        WS2[129 * WSTR + idx] = 0u;
    __syncthreads();   // zred reads done; WS2 complete

    // ====== Phase 2: out = phiQ x [Sdm | Z], ldmatrix fragments ======
    uint32_t* WQ = stage;               // 2 buffers of [64][QSTR]
    const int s0 = (w & 1) * 32;
    const int m0 = (w >> 1) * 32;

#define STAGEQ(buf_) do {                                                   \
        _Pragma("unroll")                                                   \
        for (int j_ = 0; j_ < 8; ++j_) {                                    \
            const int r_ = lrow + 8 * j_;                                   \
            float p0 = phi_elu1(fmaf(qreg[j_].x, sc4.x, bi4.x));            \
            float p1 = phi_elu1(fmaf(qreg[j_].y, sc4.y, bi4.y));            \
            float p2 = phi_elu1(fmaf(qreg[j_].z, sc4.z, bi4.z));            \
            float p3 = phi_elu1(fmaf(qreg[j_].w, sc4.w, bi4.w));            \
            uint2 qu = make_uint2(pk2(p0, p1), pk2(p2, p3));                \
            *(uint2*)((buf_) + r_ * QSTR + 2 * lane) = qu;                  \
        }                                                                   \
    } while (0)

#define PREFQ(cidx) do {                                                    \
        const float* qc_ = qb + (long)(cidx) * 64 * DD;                     \
        _Pragma("unroll")                                                   \
        for (int j_ = 0; j_ < 8; ++j_)                                      \
            qreg[j_] = *(const float4*)(qc_ + (long)(lrow + 8 * j_) * DD + c4); \
    } while (0)

    // ldmatrix base addresses (loop-invariant per lane)
    const uint32_t base_u = smem_u32(sm);
    const uint32_t wq0u   = base_u + WQ_OFF * 4;
    const int l = lane;
    uint32_t aA[2];
    #pragma unroll
    for (int st = 0; st < 2; ++st) {
        const int rowA = s0 + st * 16 + (l & 7) + 8 * ((l >> 3) & 1);
        aA[st] = wq0u + (uint32_t)(rowA * QSTR + 4 * (l >> 4)) * 4u;
    }
    uint32_t bB[2];
    #pragma unroll
    for (int gs = 0; gs < 2; ++gs) {
        const int rowB = m0 + (gs * 2 + (l >> 4)) * 8 + (l & 7);
        bB[gs] = base_u + (uint32_t)(rowB * WSTR + 4 * ((l >> 3) & 1)) * 4u;
    }
    const uint32_t bZ = base_u + (uint32_t)((128 + (l & 7)) * WSTR + 4 * ((l >> 3) & 1)) * 4u;

    STAGEQ(WQ);            // chunk 0 -> buf0
    PREFQ(1);
    __syncthreads();

    for (int chq = 0; chq < BLK / 64; ++chq) {
        // stage next chunk into alternate buffer (overlaps mma below)
        if (chq < BLK / 64 - 1) {
            STAGEQ(WQ + ((chq + 1) & 1) * WQ_BUF);
            if (chq < BLK / 64 - 2) PREFQ(chq + 2);
        }

        const uint32_t abuf = (uint32_t)((chq & 1) * WQ_BUF) * 4u;

        float accq[2][5][4];
        #pragma unroll
        for (int st = 0; st < 2; ++st)
            #pragma unroll
            for (int mt = 0; mt < 5; ++mt)
                #pragma unroll
                for (int r = 0; r < 4; ++r) accq[st][mt][r] = 0.0f;

        #pragma unroll
        for (int kk = 0; kk < DD / 16; ++kk) {   // 8 k-steps of 16
            const uint32_t ko = 32u * kk;
            uint32_t A0[4], A1[4], B0[4], B1[4], BZ[2];
            LDSM4(A0, aA[0] + abuf + ko);
            LDSM4(A1, aA[1] + abuf + ko);
            LDSM4(B0, bB[0] + ko);
            LDSM4(B1, bB[1] + ko);
            LDSM2(BZ, bZ + ko);
            mma_f16(accq[0][0], A0, &B0[0]);
            mma_f16(accq[1][0], A1, &B0[0]);
            mma_f16(accq[0][1], A0, &B0[2]);
            mma_f16(accq[1][1], A1, &B0[2]);
            mma_f16(accq[0][2], A0, &B1[0]);
            mma_f16(accq[1][2], A1, &B1[0]);
            mma_f16(accq[0][3], A0, &B1[2]);
            mma_f16(accq[1][3], A1, &B1[2]);
            mma_f16(accq[0][4], A0, BZ);
            mma_f16(accq[1][4], A1, BZ);
        }

        // den via shuffle from lane 4g (Z col = 128 -> t==0, c0/c2)
        #pragma unroll
        for (int st = 0; st < 2; ++st) {
            const float z0 = __shfl_sync(0xffffffffu, accq[st][4][0], lane & 28);
            const float z8 = __shfl_sync(0xffffffffu, accq[st][4][2], lane & 28);
            const float i0 = 1.0f / (z0 + EPS_F);
            const float i1 = 1.0f / (z8 + EPS_F);
            const int rr = s0 + st * 16 + g;
            const int r0 = chq * 64 + rr;
            #pragma unroll
            for (int mt = 0; mt < 4; ++mt) {
                const int m = m0 + mt * 8 + 2 * t;
                *(float2*)(ob + (long)r0 * DD + m) =
                    make_float2(accq[st][mt][0] * i0, accq[st][mt][1] * i0);
                *(float2*)(ob + (long)(r0 + 8) * DD + m) =
                    make_float2(accq[st][mt][2] * i1, accq[st][mt][3] * i1);
            }
        }
        __syncthreads();   // protect buffer (chq+2)&1 from pending reads
    }
}

extern "C" void kernel_launch(void* const* d_in, const int* in_sizes, int n_in,
                              void* d_out, int out_size) {
    const float* q  = (const float*)d_in[0];
    const float* k  = (const float*)d_in[1];
    const float* v  = (const float*)d_in[2];
    const float* sc = (const float*)d_in[3];
    const float* bi = (const float*)d_in[4];
    float* out = (float*)d_out;

    cudaFuncSetAttribute(lin_attn_ldsm,
                         cudaFuncAttributeMaxDynamicSharedMemorySize, SMEM_BYTES);
    lin_attn_ldsm<<<NCTA, NT, SMEM_BYTES>>>(q, k, v, sc, bi, out);
}